// round 14
// baseline (speedup 1.0000x reference)
#include <cuda_runtime.h>
#include <cuda_bf16.h>
#include <cuda_fp16.h>
#include <cstdint>

#define S_LEN 2048
#define B_SZ 4
#define NH 16
#define DH 64
#define DM 1024
#define MROWS (B_SZ * S_LEN)   // 8192
#define GK 1024

// ---------------- scratch (device globals; device-code references ONLY) -----
// Compacted-K/V padding rows (rank >= kcnt) are never written; they stay at
// the guaranteed zero-init of __device__ globals, and cmask=-1e30 zeroes them.
__device__ int   g_kcnt[B_SZ];
__device__ int   g_rank[B_SZ * S_LEN];    // global dest row or -1
__device__ float g_cmask[B_SZ * S_LEN];

__device__ __half g_xhi[MROWS * DM];
__device__ __half g_ahi[MROWS * DM];
__device__ __half g_wth[4 * DM * DM];     // W^T fp16, [N][K] K-major

__device__ __half g_qhi[MROWS * DM];
__device__ __half g_ckhi[MROWS * DM];     // compacted K (written by GEMM)
__device__ __half g_cvhi[MROWS * DM];     // compacted V (written by GEMM)

// ---------------- PTX helpers ------------------------------------------------
__device__ __forceinline__ uint32_t smem_u32(const void* p) {
    uint32_t a;
    asm("{ .reg .u64 t; cvta.to.shared.u64 t, %1; cvt.u32.u64 %0, t; }"
        : "=r"(a) : "l"(p));
    return a;
}

#define MMA_F16(c, a, b0, b1)                                               \
    asm volatile("mma.sync.aligned.m16n8k16.row.col.f32.f16.f16.f32 "       \
                 "{%0,%1,%2,%3}, {%4,%5,%6,%7}, {%8,%9}, {%0,%1,%2,%3};"    \
                 : "+f"((c)[0]), "+f"((c)[1]), "+f"((c)[2]), "+f"((c)[3])   \
                 : "r"((a)[0]), "r"((a)[1]), "r"((a)[2]), "r"((a)[3]),      \
                   "r"(b0), "r"(b1))

#define LDMATRIX_X4_TRANS(r0, r1, r2, r3, addr)                             \
    asm volatile("ldmatrix.sync.aligned.m8n8.x4.trans.shared.b16 "          \
                 "{%0,%1,%2,%3}, [%4];"                                     \
                 : "=r"(r0), "=r"(r1), "=r"(r2), "=r"(r3) : "r"(addr))

__device__ __forceinline__ void cpa16(uint32_t dst, const void* src) {
    asm volatile("cp.async.ca.shared.global [%0], [%1], 16;"
                 :: "r"(dst), "l"(src));
}
#define CP_COMMIT()  asm volatile("cp.async.commit_group;" ::: "memory")
#define CP_WAIT(n)   asm volatile("cp.async.wait_group %0;" :: "n"(n) : "memory")

__device__ __forceinline__ uint32_t pack_h2(float a, float b) {
    __half2 h = __floats2half2_rn(a, b);
    return *(uint32_t*)&h;
}

// ---------------- mask scan (dtype detect fused in) ---------------------------
__global__ __launch_bounds__(256)
void scan_mask_kernel(const void* __restrict__ mraw) {
    __shared__ int ssum[256];
    __shared__ int s_nonbin, s_off;
    const int b = blockIdx.x;
    const int tid = threadIdx.x;

    // local dtype detection over the first 8192 bytes (valid for int8/i32/f32)
    if (tid == 0) { s_nonbin = 0; s_off = 0; }
    __syncthreads();
    {
        const unsigned char* mb = (const unsigned char*)mraw;
        int nb = 0, off = 0;
        for (int i = tid; i < B_SZ * S_LEN; i += 256) {
            unsigned char v = mb[i];
            if (v > 1) nb = 1;
            if ((i & 3) && v) off = 1;
        }
        if (nb) atomicOr(&s_nonbin, 1);
        if (off) atomicOr(&s_off, 1);
    }
    __syncthreads();
    const int mode = s_nonbin ? 2 : (s_off ? 1 : 0);

    int flags[8], loc = 0;
#pragma unroll
    for (int j = 0; j < 8; ++j) {
        int i = b * S_LEN + tid * 8 + j;
        bool t;
        if (mode == 0)      t = ((const int*)mraw)[i] != 0;
        else if (mode == 1) t = ((const unsigned char*)mraw)[i] != 0;
        else                t = ((const float*)mraw)[i] != 0.0f;
        flags[j] = t ? 1 : 0;
        loc += flags[j];
    }
    ssum[tid] = loc;
    __syncthreads();
    for (int off = 1; off < 256; off <<= 1) {
        int v = (tid >= off) ? ssum[tid - off] : 0;
        __syncthreads();
        ssum[tid] += v;
        __syncthreads();
    }
    int base = (tid > 0) ? ssum[tid - 1] : 0;
    const int cnt = ssum[255];
#pragma unroll
    for (int j = 0; j < 8; ++j) {
        int i = tid * 8 + j;
        g_rank[b * S_LEN + i] = flags[j] ? (b * S_LEN + base++) : -1;
        g_cmask[b * S_LEN + i] = (i < cnt) ? 0.0f : -1e30f;
    }
    if (tid == 255) g_kcnt[b] = cnt;
}

// ---------------- fp32 -> fp16 (x), 8 elems/thread ----------------------------
__global__ __launch_bounds__(256)
void conv_x_kernel(const float4* __restrict__ src) {
    int i = blockIdx.x * blockDim.x + threadIdx.x;   // MROWS*DM/8 = 1M
    float4 a = src[2 * i], c = src[2 * i + 1];
    __half2 h0 = __floats2half2_rn(a.x, a.y);
    __half2 h1 = __floats2half2_rn(a.z, a.w);
    __half2 h2 = __floats2half2_rn(c.x, c.y);
    __half2 h3 = __floats2half2_rn(c.z, c.w);
    uint4 o = { *(uint32_t*)&h0, *(uint32_t*)&h1, *(uint32_t*)&h2, *(uint32_t*)&h3 };
    *(uint4*)&g_xhi[(size_t)i * 8] = o;
}

// ---------------- W transpose + fp16 -----------------------------------------
__global__ __launch_bounds__(256)
void prep_w_kernel(const float* __restrict__ Wq, const float* __restrict__ Wk,
                   const float* __restrict__ Wv, const float* __restrict__ Wo) {
    __shared__ float t[32][33];
    int z = blockIdx.z;
    const float* W = (z == 0) ? Wq : (z == 1) ? Wk : (z == 2) ? Wv : Wo;
    __half* oh = g_wth + (size_t)z * DM * DM;
    int x0 = blockIdx.x * 32, y0 = blockIdx.y * 32;
    int tx = threadIdx.x, ty = threadIdx.y;   // (32, 8)
#pragma unroll
    for (int j = 0; j < 4; ++j)
        t[ty + j * 8][tx] = W[(size_t)(y0 + ty + j * 8) * DM + x0 + tx];
    __syncthreads();
#pragma unroll
    for (int j = 0; j < 4; ++j) {
        float v = t[tx][ty + j * 8];
        oh[(size_t)(x0 + ty + j * 8) * DM + y0 + tx] = __float2half_rn(v);
    }
}

// ---------------- mma.sync fp16 GEMM, 3-stage cp.async, 1 sync/iter ----------
#define AS_STRIDE 40
#define SEG (128 * AS_STRIDE)
#define SEGB (SEG * 2)
#define STAGEB (2 * SEGB)            // A, B
#define GEMM_SMEM (3 * STAGEB)       // 61440 bytes
#define NKT (GK / 32)                // 32

template <bool HALF_OUT>
__device__ __forceinline__ void gemm_tc_body(const __half* __restrict__ Ah_g,
                                             const __half* __restrict__ Bh_g,
                                             const float* __restrict__ bias,
                                             float* __restrict__ Cf,
                                             __half* __restrict__ Chi,
                                             const int* __restrict__ remap) {
    extern __shared__ __half smh[];

    const int tid  = threadIdx.x;
    const int lane = tid & 31, warp = tid >> 5;
    const int wm = (warp & 3) * 32;
    const int wn = (warp >> 2) * 64;
    const int m0 = blockIdx.y * 128;
    const int n0 = blockIdx.x * 128;
    const int grp = lane >> 2;
    const int tig = lane & 3;

    const uint32_t sb = smem_u32(smh);
    const int r0l = tid >> 2, q0l = tid & 3;
    const int r1l = (tid + 256) >> 2;
    const uint32_t soff0 = (uint32_t)(r0l * AS_STRIDE + q0l * 8) * 2;
    const uint32_t soff1 = (uint32_t)(r1l * AS_STRIDE + q0l * 8) * 2;

    float acc[2][8][4];
#pragma unroll
    for (int mt = 0; mt < 2; ++mt)
#pragma unroll
        for (int nt = 0; nt < 8; ++nt)
#pragma unroll
            for (int e = 0; e < 4; ++e) acc[mt][nt][e] = 0.0f;

    auto load_stage = [&](int kt, int s) {
        const uint32_t base = sb + (uint32_t)s * STAGEB;
        const size_t ga0 = (size_t)(m0 + r0l) * GK + kt * 32 + q0l * 8;
        const size_t ga1 = (size_t)(m0 + r1l) * GK + kt * 32 + q0l * 8;
        const size_t gb0 = (size_t)(n0 + r0l) * GK + kt * 32 + q0l * 8;
        const size_t gb1 = (size_t)(n0 + r1l) * GK + kt * 32 + q0l * 8;
        cpa16(base + soff0,        &Ah_g[ga0]);
        cpa16(base + SEGB + soff0, &Bh_g[gb0]);
        cpa16(base + soff1,        &Ah_g[ga1]);
        cpa16(base + SEGB + soff1, &Bh_g[gb1]);
    };

    load_stage(0, 0); CP_COMMIT();
    load_stage(1, 1); CP_COMMIT();

    for (int kt = 0; kt < NKT; ++kt) {
        const int cur = kt % 3;
        if (kt + 1 < NKT) { CP_WAIT(1); } else { CP_WAIT(0); }
        __syncthreads();   // kt's tile ready; all warps done with stage (kt-1)%3
        if (kt + 2 < NKT) { load_stage(kt + 2, (kt + 2) % 3); CP_COMMIT(); }

        const __half* Ah = smh + (size_t)cur * 2 * SEG;
        const __half* Bs = Ah + SEG;

#pragma unroll
        for (int ks = 0; ks < 2; ++ks) {
            const int kof = ks * 16 + tig * 2;
            uint32_t bh[8][2];
#pragma unroll
            for (int nt = 0; nt < 8; ++nt) {
                const int nr = wn + nt * 8 + grp;
                bh[nt][0] = *(const uint32_t*)&Bs[nr * AS_STRIDE + kof];
                bh[nt][1] = *(const uint32_t*)&Bs[nr * AS_STRIDE + kof + 8];
            }
#pragma unroll
            for (int mt = 0; mt < 2; ++mt) {
                const int mr = wm + mt * 16 + grp;
                uint32_t a_h[4];
                a_h[0] = *(const uint32_t*)&Ah[mr * AS_STRIDE + kof];
                a_h[1] = *(const uint32_t*)&Ah[(mr + 8) * AS_STRIDE + kof];
                a_h[2] = *(const uint32_t*)&Ah[mr * AS_STRIDE + kof + 8];
                a_h[3] = *(const uint32_t*)&Ah[(mr + 8) * AS_STRIDE + kof + 8];
#pragma unroll
                for (int nt = 0; nt < 8; ++nt)
                    MMA_F16(acc[mt][nt], a_h, bh[nt][0], bh[nt][1]);
            }
        }
    }

#pragma unroll
    for (int mt = 0; mt < 2; ++mt) {
        const int r = m0 + wm + mt * 16 + grp;
        int d0 = r, d1 = r + 8;
        if (HALF_OUT && remap) {
            d0 = remap[r];
            d1 = remap[r + 8];
        }
#pragma unroll
        for (int nt = 0; nt < 8; ++nt) {
            int c = n0 + wn + nt * 8 + tig * 2;
            float2 bb = *(const float2*)&bias[c];
            float v0x = acc[mt][nt][0] + bb.x, v0y = acc[mt][nt][1] + bb.y;
            float v1x = acc[mt][nt][2] + bb.x, v1y = acc[mt][nt][3] + bb.y;
            if constexpr (HALF_OUT) {
                if (d0 >= 0) {
                    __half2 hp; hp.x = __float2half_rn(v0x); hp.y = __float2half_rn(v0y);
                    *(__half2*)&Chi[(size_t)d0 * DM + c] = hp;
                }
                if (d1 >= 0) {
                    __half2 hq; hq.x = __float2half_rn(v1x); hq.y = __float2half_rn(v1y);
                    *(__half2*)&Chi[(size_t)d1 * DM + c] = hq;
                }
            } else {
                float2 o0 = { v0x, v0y }, o1 = { v1x, v1y };
                *(float2*)&Cf[(size_t)r * DM + c] = o0;
                *(float2*)&Cf[(size_t)(r + 8) * DM + c] = o1;
            }
        }
    }
}

__global__ __launch_bounds__(256, 2)
void qkv_tc_kernel(const float* __restrict__ bq, const float* __restrict__ bk,
                   const float* __restrict__ bv) {
    int z = blockIdx.z;
    const __half* Bh = g_wth + (size_t)z * DM * DM;
    const float* bias = (z == 0) ? bq : (z == 1) ? bk : bv;
    __half* Chi = (z == 0) ? g_qhi : (z == 1) ? g_ckhi : g_cvhi;
    const int* remap = (z == 0) ? nullptr : g_rank;
    gemm_tc_body<true>(g_xhi, Bh, bias, nullptr, Chi, remap);
}

__global__ __launch_bounds__(256, 2)
void oproj_tc_kernel(const float* __restrict__ bo, float* __restrict__ out) {
    gemm_tc_body<false>(g_ahi, g_wth + (size_t)3 * DM * DM, bo, out,
                        nullptr, nullptr);
}

// ---------------- flash attention: 3-stage cp.async, 1 sync/iter -------------
#define KST 72
#define ASEG (64 * KST)
#define ASTG (2 * ASEG)              // Kh, Vh
#define ATT_SMEM (3 * ASTG * 2 + 3 * 64 * 4)   // 56064 bytes

__global__ __launch_bounds__(256, 2)
void attn_tc_kernel() {
    extern __shared__ __half asmem[];
    float* Msb = (float*)(asmem + 3 * ASTG);   // [3][64]

    const int tid = threadIdx.x;
    const int lane = tid & 31, warp = tid >> 5;
    const int grp = lane >> 2, tig = lane & 3;
    const int qb = blockIdx.x, bh = blockIdx.y;
    const int b = bh >> 4, h = bh & 15;
    const int row0 = b * S_LEN + qb * 128;
    const int wm = warp * 16;

    const int cnt = g_kcnt[b];
    const int nblk = (cnt + 63) >> 6;

    const uint32_t sb = smem_u32(asmem);
    const uint32_t msb = smem_u32(Msb);
    const int pr = tid >> 3, pc = (tid & 7) * 8;

    uint32_t qh[4][4];
    {
        const size_t r0 = (size_t)(row0 + wm + grp) * DM;
        const size_t r1 = r0 + 8 * DM;
#pragma unroll
        for (int kc = 0; kc < 4; ++kc) {
            int d = h * DH + kc * 16 + tig * 2;
            qh[kc][0] = *(const uint32_t*)&g_qhi[r0 + d];
            qh[kc][1] = *(const uint32_t*)&g_qhi[r1 + d];
            qh[kc][2] = *(const uint32_t*)&g_qhi[r0 + d + 8];
            qh[kc][3] = *(const uint32_t*)&g_qhi[r1 + d + 8];
        }
    }

    float o[8][4];
#pragma unroll
    for (int nt = 0; nt < 8; ++nt)
#pragma unroll
        for (int e = 0; e < 4; ++e) o[nt][e] = 0.0f;
    float m0 = -1e30f, m1 = -1e30f, l0 = 0.0f, l1 = 0.0f;

    auto load_stage = [&](int kb, int s) {
        const size_t gbase = (size_t)(b * S_LEN + kb * 64) * DM + h * DH;
        const uint32_t sbase = sb + (uint32_t)s * (ASTG * 2);
        const size_t g0 = gbase + (size_t)pr * DM + pc;
        const size_t g1 = gbase + (size_t)(pr + 32) * DM + pc;
        const uint32_t s0 = (uint32_t)(pr * KST + pc) * 2;
        const uint32_t s1 = (uint32_t)((pr + 32) * KST + pc) * 2;
        cpa16(sbase + s0,            &g_ckhi[g0]);
        cpa16(sbase + s1,            &g_ckhi[g1]);
        cpa16(sbase + ASEG * 2 + s0, &g_cvhi[g0]);
        cpa16(sbase + ASEG * 2 + s1, &g_cvhi[g1]);
        if (tid < 16)
            cpa16(msb + (uint32_t)s * 256 + tid * 16,
                  &g_cmask[b * S_LEN + kb * 64 + tid * 4]);
    };

    load_stage(0, 0); CP_COMMIT();
    if (nblk > 1) { load_stage(1, 1); CP_COMMIT(); }

    for (int kb = 0; kb < nblk; ++kb) {
        const int cur = kb % 3;
        if (kb + 1 < nblk) { CP_WAIT(1); } else { CP_WAIT(0); }
        __syncthreads();
        if (kb + 2 < nblk) { load_stage(kb + 2, (kb + 2) % 3); CP_COMMIT(); }

        const __half* Kh = asmem + (size_t)cur * ASTG;
        const __half* Vh = Kh + ASEG;
        const float* Ms = Msb + cur * 64;

        float s[8][4];
#pragma unroll
        for (int nt = 0; nt < 8; ++nt)
#pragma unroll
            for (int e = 0; e < 4; ++e) s[nt][e] = 0.0f;

#pragma unroll
        for (int kc = 0; kc < 4; ++kc) {
            const int kof = kc * 16 + tig * 2;
#pragma unroll
            for (int nt = 0; nt < 8; ++nt) {
                const int nr = nt * 8 + grp;
                uint32_t b0 = *(const uint32_t*)&Kh[nr * KST + kof];
                uint32_t b1 = *(const uint32_t*)&Kh[nr * KST + kof + 8];
                MMA_F16(s[nt], qh[kc], b0, b1);
            }
        }

        float tmax0 = -1e30f, tmax1 = -1e30f;
#pragma unroll
        for (int nt = 0; nt < 8; ++nt) {
            float2 mv = *(const float2*)&Ms[nt * 8 + tig * 2];
            s[nt][0] = fmaf(s[nt][0], 0.125f, mv.x);
            s[nt][1] = fmaf(s[nt][1], 0.125f, mv.y);
            s[nt][2] = fmaf(s[nt][2], 0.125f, mv.x);
            s[nt][3] = fmaf(s[nt][3], 0.125f, mv.y);
            tmax0 = fmaxf(tmax0, fmaxf(s[nt][0], s[nt][1]));
            tmax1 = fmaxf(tmax1, fmaxf(s[nt][2], s[nt][3]));
        }
        tmax0 = fmaxf(tmax0, __shfl_xor_sync(0xffffffffu, tmax0, 1));
        tmax0 = fmaxf(tmax0, __shfl_xor_sync(0xffffffffu, tmax0, 2));
        tmax1 = fmaxf(tmax1, __shfl_xor_sync(0xffffffffu, tmax1, 1));
        tmax1 = fmaxf(tmax1, __shfl_xor_sync(0xffffffffu, tmax1, 2));

        float mn0 = fmaxf(m0, tmax0), mn1 = fmaxf(m1, tmax1);
        float al0 = __expf(m0 - mn0), al1 = __expf(m1 - mn1);
        m0 = mn0; m1 = mn1;

        float rs0 = 0.0f, rs1 = 0.0f;
        uint32_t pa[8], pb[8];
#pragma unroll
        for (int nt = 0; nt < 8; ++nt) {
            float p0 = __expf(s[nt][0] - mn0);
            float p1 = __expf(s[nt][1] - mn0);
            float p2 = __expf(s[nt][2] - mn1);
            float p3 = __expf(s[nt][3] - mn1);
            rs0 += p0 + p1; rs1 += p2 + p3;
            pa[nt] = pack_h2(p0, p1);
            pb[nt] = pack_h2(p2, p3);
        }
        rs0 += __shfl_xor_sync(0xffffffffu, rs0, 1);
        rs0 += __shfl_xor_sync(0xffffffffu, rs0, 2);
        rs1 += __shfl_xor_sync(0xffffffffu, rs1, 1);
        rs1 += __shfl_xor_sync(0xffffffffu, rs1, 2);
        l0 = l0 * al0 + rs0;
        l1 = l1 * al1 + rs1;

#pragma unroll
        for (int nt = 0; nt < 8; ++nt) {
            o[nt][0] *= al0; o[nt][1] *= al0;
            o[nt][2] *= al1; o[nt][3] *= al1;
        }

        const int lrow = (lane & 7) + 8 * ((lane >> 3) & 1);
        const int lcol = 8 * (lane >> 4);
#pragma unroll
        for (int kc2 = 0; kc2 < 4; ++kc2) {
            uint32_t a[4] = { pa[kc2 * 2], pb[kc2 * 2], pa[kc2 * 2 + 1], pb[kc2 * 2 + 1] };
#pragma unroll
            for (int dp = 0; dp < 4; ++dp) {
                uint32_t v0, v1, v2, v3;
                uint32_t ad = smem_u32(&Vh[(kc2 * 16 + lrow) * KST + dp * 16 + lcol]);
                LDMATRIX_X4_TRANS(v0, v1, v2, v3, ad);
                MMA_F16(o[dp * 2],     a, v0, v1);
                MMA_F16(o[dp * 2 + 1], a, v2, v3);
            }
        }
    }

    // ---- epilogue: normalize, write fp16 for oproj ----
    float inv0 = 1.0f / l0, inv1 = 1.0f / l1;
    const size_t r0 = (size_t)(row0 + wm + grp) * DM;
    const size_t r1 = r0 + 8 * DM;
#pragma unroll
    for (int nt = 0; nt < 8; ++nt) {
        int c = h * DH + nt * 8 + tig * 2;
        __half2 hp; hp.x = __float2half_rn(o[nt][0] * inv0);
                    hp.y = __float2half_rn(o[nt][1] * inv0);
        *(__half2*)&g_ahi[r0 + c] = hp;
        __half2 hq; hq.x = __float2half_rn(o[nt][2] * inv1);
                    hq.y = __float2half_rn(o[nt][3] * inv1);
        *(__half2*)&g_ahi[r1 + c] = hq;
    }
}

// ---------------- launch -----------------------------------------------------
extern "C" void kernel_launch(void* const* d_in, const int* in_sizes, int n_in,
                              void* d_out, int out_size) {
    const float* x  = (const float*)d_in[0];
    const void*  mk = d_in[1];
    const float* Wq = (const float*)d_in[2];
    const float* bq = (const float*)d_in[3];
    const float* Wk = (const float*)d_in[4];
    const float* bk = (const float*)d_in[5];
    const float* Wv = (const float*)d_in[6];
    const float* bv = (const float*)d_in[7];
    const float* Wo = (const float*)d_in[8];
    const float* bo = (const float*)d_in[9];
    float* out = (float*)d_out;

    scan_mask_kernel<<<B_SZ, 256>>>(mk);

    prep_w_kernel<<<dim3(32, 32, 4), dim3(32, 8)>>>(Wq, Wk, Wv, Wo);
    conv_x_kernel<<<MROWS * DM / 8 / 256, 256>>>((const float4*)x);

    cudaFuncSetAttribute(qkv_tc_kernel,
                         cudaFuncAttributeMaxDynamicSharedMemorySize, GEMM_SMEM);
    cudaFuncSetAttribute(oproj_tc_kernel,
                         cudaFuncAttributeMaxDynamicSharedMemorySize, GEMM_SMEM);
    cudaFuncSetAttribute(attn_tc_kernel,
                         cudaFuncAttributeMaxDynamicSharedMemorySize, ATT_SMEM);

    qkv_tc_kernel<<<dim3(DM / 128, MROWS / 128, 3), 256, GEMM_SMEM>>>(bq, bk, bv);

    attn_tc_kernel<<<dim3(S_LEN / 128, B_SZ * NH), 256, ATT_SMEM>>>();

    oproj_tc_kernel<<<dim3(DM / 128, MROWS / 128), 256, GEMM_SMEM>>>(bo, out);
}

// round 15
// speedup vs baseline: 1.5160x; 1.5160x over previous
#include <cuda_runtime.h>
#include <cuda_bf16.h>
#include <cuda_fp16.h>
#include <cstdint>

#define S_LEN 2048
#define B_SZ 4
#define NH 16
#define DH 64
#define DM 1024
#define MROWS (B_SZ * S_LEN)   // 8192
#define GK 1024

// ---------------- scratch (device globals; device-code references ONLY) -----
// Compacted-K/V padding rows (rank >= kcnt) are never written; they stay at
// the guaranteed zero-init of __device__ globals, and cmask=-1e30 zeroes them.
__device__ int   g_kcnt[B_SZ];
__device__ int   g_rank[B_SZ * S_LEN];    // global dest row or -1
__device__ float g_cmask[B_SZ * S_LEN];

__device__ __half g_xhi[MROWS * DM];
__device__ __half g_ahi[MROWS * DM];
__device__ __half g_wth[4 * DM * DM];     // W^T fp16, [N][K] K-major

__device__ __half g_qhi[MROWS * DM];
__device__ __half g_ckhi[MROWS * DM];     // compacted K (written by GEMM)
__device__ __half g_cvhi[MROWS * DM];     // compacted V (written by GEMM)

// ---------------- PTX helpers ------------------------------------------------
__device__ __forceinline__ uint32_t smem_u32(const void* p) {
    uint32_t a;
    asm("{ .reg .u64 t; cvta.to.shared.u64 t, %1; cvt.u32.u64 %0, t; }"
        : "=r"(a) : "l"(p));
    return a;
}

#define MMA_F16(c, a, b0, b1)                                               \
    asm volatile("mma.sync.aligned.m16n8k16.row.col.f32.f16.f16.f32 "       \
                 "{%0,%1,%2,%3}, {%4,%5,%6,%7}, {%8,%9}, {%0,%1,%2,%3};"    \
                 : "+f"((c)[0]), "+f"((c)[1]), "+f"((c)[2]), "+f"((c)[3])   \
                 : "r"((a)[0]), "r"((a)[1]), "r"((a)[2]), "r"((a)[3]),      \
                   "r"(b0), "r"(b1))

#define LDMATRIX_X4_TRANS(r0, r1, r2, r3, addr)                             \
    asm volatile("ldmatrix.sync.aligned.m8n8.x4.trans.shared.b16 "          \
                 "{%0,%1,%2,%3}, [%4];"                                     \
                 : "=r"(r0), "=r"(r1), "=r"(r2), "=r"(r3) : "r"(addr))

__device__ __forceinline__ void cpa16(uint32_t dst, const void* src) {
    asm volatile("cp.async.ca.shared.global [%0], [%1], 16;"
                 :: "r"(dst), "l"(src));
}
#define CP_COMMIT()  asm volatile("cp.async.commit_group;" ::: "memory")
#define CP_WAIT(n)   asm volatile("cp.async.wait_group %0;" :: "n"(n) : "memory")

__device__ __forceinline__ uint32_t pack_h2(float a, float b) {
    __half2 h = __floats2half2_rn(a, b);
    return *(uint32_t*)&h;
}

// ---------------- mask scan (dtype detect fused in) ---------------------------
__global__ __launch_bounds__(256)
void scan_mask_kernel(const void* __restrict__ mraw) {
    __shared__ int ssum[256];
    __shared__ int s_nonbin, s_off;
    const int b = blockIdx.x;
    const int tid = threadIdx.x;

    if (tid == 0) { s_nonbin = 0; s_off = 0; }
    __syncthreads();
    {
        const unsigned char* mb = (const unsigned char*)mraw;
        int nb = 0, off = 0;
        for (int i = tid; i < B_SZ * S_LEN; i += 256) {
            unsigned char v = mb[i];
            if (v > 1) nb = 1;
            if ((i & 3) && v) off = 1;
        }
        if (nb) atomicOr(&s_nonbin, 1);
        if (off) atomicOr(&s_off, 1);
    }
    __syncthreads();
    const int mode = s_nonbin ? 2 : (s_off ? 1 : 0);

    int flags[8], loc = 0;
#pragma unroll
    for (int j = 0; j < 8; ++j) {
        int i = b * S_LEN + tid * 8 + j;
        bool t;
        if (mode == 0)      t = ((const int*)mraw)[i] != 0;
        else if (mode == 1) t = ((const unsigned char*)mraw)[i] != 0;
        else                t = ((const float*)mraw)[i] != 0.0f;
        flags[j] = t ? 1 : 0;
        loc += flags[j];
    }
    ssum[tid] = loc;
    __syncthreads();
    for (int off = 1; off < 256; off <<= 1) {
        int v = (tid >= off) ? ssum[tid - off] : 0;
        __syncthreads();
        ssum[tid] += v;
        __syncthreads();
    }
    int base = (tid > 0) ? ssum[tid - 1] : 0;
    const int cnt = ssum[255];
#pragma unroll
    for (int j = 0; j < 8; ++j) {
        int i = tid * 8 + j;
        g_rank[b * S_LEN + i] = flags[j] ? (b * S_LEN + base++) : -1;
        g_cmask[b * S_LEN + i] = (i < cnt) ? 0.0f : -1e30f;
    }
    if (tid == 255) g_kcnt[b] = cnt;
}

// ---------------- fp32 -> fp16 (x), 8 elems/thread ----------------------------
__global__ __launch_bounds__(256)
void conv_x_kernel(const float4* __restrict__ src) {
    int i = blockIdx.x * blockDim.x + threadIdx.x;   // MROWS*DM/8
    float4 a = src[2 * i], c = src[2 * i + 1];
    __half2 h0 = __floats2half2_rn(a.x, a.y);
    __half2 h1 = __floats2half2_rn(a.z, a.w);
    __half2 h2 = __floats2half2_rn(c.x, c.y);
    __half2 h3 = __floats2half2_rn(c.z, c.w);
    uint4 o = { *(uint32_t*)&h0, *(uint32_t*)&h1, *(uint32_t*)&h2, *(uint32_t*)&h3 };
    *(uint4*)&g_xhi[(size_t)i * 8] = o;
}

// ---------------- W transpose + fp16 -----------------------------------------
__global__ __launch_bounds__(256)
void prep_w_kernel(const float* __restrict__ Wq, const float* __restrict__ Wk,
                   const float* __restrict__ Wv, const float* __restrict__ Wo) {
    __shared__ float t[32][33];
    int z = blockIdx.z;
    const float* W = (z == 0) ? Wq : (z == 1) ? Wk : (z == 2) ? Wv : Wo;
    __half* oh = g_wth + (size_t)z * DM * DM;
    int x0 = blockIdx.x * 32, y0 = blockIdx.y * 32;
    int tx = threadIdx.x, ty = threadIdx.y;   // (32, 8)
#pragma unroll
    for (int j = 0; j < 4; ++j)
        t[ty + j * 8][tx] = W[(size_t)(y0 + ty + j * 8) * DM + x0 + tx];
    __syncthreads();
#pragma unroll
    for (int j = 0; j < 4; ++j) {
        float v = t[tx][ty + j * 8];
        oh[(size_t)(x0 + ty + j * 8) * DM + y0 + tx] = __float2half_rn(v);
    }
}

// ---------------- mma.sync fp16 GEMM, 2-stage cp.async (proven R13) ----------
#define AS_STRIDE 40
#define SEG (128 * AS_STRIDE)
#define SEGB (SEG * 2)
#define STAGEB (2 * SEGB)            // A, B
#define GEMM_SMEM (2 * STAGEB)       // 40960 bytes

template <bool HALF_OUT>
__device__ __forceinline__ void gemm_tc_body(const __half* __restrict__ Ah_g,
                                             const __half* __restrict__ Bh_g,
                                             const float* __restrict__ bias,
                                             float* __restrict__ Cf,
                                             __half* __restrict__ Chi,
                                             const int* __restrict__ remap) {
    extern __shared__ __half smh[];

    const int tid  = threadIdx.x;
    const int lane = tid & 31, warp = tid >> 5;
    const int wm = (warp & 3) * 32;
    const int wn = (warp >> 2) * 64;
    const int m0 = blockIdx.y * 128;
    const int n0 = blockIdx.x * 128;
    const int grp = lane >> 2;
    const int tig = lane & 3;

    const uint32_t sb = smem_u32(smh);
    const int r0l = tid >> 2, q0l = tid & 3;
    const int r1l = (tid + 256) >> 2;
    const uint32_t soff0 = (uint32_t)(r0l * AS_STRIDE + q0l * 8) * 2;
    const uint32_t soff1 = (uint32_t)(r1l * AS_STRIDE + q0l * 8) * 2;

    float acc[2][8][4];
#pragma unroll
    for (int mt = 0; mt < 2; ++mt)
#pragma unroll
        for (int nt = 0; nt < 8; ++nt)
#pragma unroll
            for (int e = 0; e < 4; ++e) acc[mt][nt][e] = 0.0f;

    auto load_stage = [&](int kt, int s) {
        const uint32_t base = sb + (uint32_t)s * STAGEB;
        const size_t ga0 = (size_t)(m0 + r0l) * GK + kt * 32 + q0l * 8;
        const size_t ga1 = (size_t)(m0 + r1l) * GK + kt * 32 + q0l * 8;
        const size_t gb0 = (size_t)(n0 + r0l) * GK + kt * 32 + q0l * 8;
        const size_t gb1 = (size_t)(n0 + r1l) * GK + kt * 32 + q0l * 8;
        cpa16(base + soff0,        &Ah_g[ga0]);
        cpa16(base + SEGB + soff0, &Bh_g[gb0]);
        cpa16(base + soff1,        &Ah_g[ga1]);
        cpa16(base + SEGB + soff1, &Bh_g[gb1]);
    };

    load_stage(0, 0);
    CP_COMMIT();

    for (int kt = 0; kt < GK / 32; ++kt) {
        const int cur = kt & 1;
        if (kt + 1 < GK / 32) {
            load_stage(kt + 1, cur ^ 1);
            CP_COMMIT();
            CP_WAIT(1);
        } else {
            CP_WAIT(0);
        }
        __syncthreads();

        const __half* Ah = smh + (size_t)cur * 2 * SEG;
        const __half* Bs = Ah + SEG;

#pragma unroll
        for (int ks = 0; ks < 2; ++ks) {
            const int kof = ks * 16 + tig * 2;
            uint32_t bh[8][2];
#pragma unroll
            for (int nt = 0; nt < 8; ++nt) {
                const int nr = wn + nt * 8 + grp;
                bh[nt][0] = *(const uint32_t*)&Bs[nr * AS_STRIDE + kof];
                bh[nt][1] = *(const uint32_t*)&Bs[nr * AS_STRIDE + kof + 8];
            }
#pragma unroll
            for (int mt = 0; mt < 2; ++mt) {
                const int mr = wm + mt * 16 + grp;
                uint32_t a_h[4];
                a_h[0] = *(const uint32_t*)&Ah[mr * AS_STRIDE + kof];
                a_h[1] = *(const uint32_t*)&Ah[(mr + 8) * AS_STRIDE + kof];
                a_h[2] = *(const uint32_t*)&Ah[mr * AS_STRIDE + kof + 8];
                a_h[3] = *(const uint32_t*)&Ah[(mr + 8) * AS_STRIDE + kof + 8];
#pragma unroll
                for (int nt = 0; nt < 8; ++nt)
                    MMA_F16(acc[mt][nt], a_h, bh[nt][0], bh[nt][1]);
            }
        }
        __syncthreads();
    }

#pragma unroll
    for (int mt = 0; mt < 2; ++mt) {
        const int r = m0 + wm + mt * 16 + grp;
        int d0 = r, d1 = r + 8;
        if (HALF_OUT && remap) {
            d0 = remap[r];
            d1 = remap[r + 8];
        }
#pragma unroll
        for (int nt = 0; nt < 8; ++nt) {
            int c = n0 + wn + nt * 8 + tig * 2;
            float2 bb = *(const float2*)&bias[c];
            float v0x = acc[mt][nt][0] + bb.x, v0y = acc[mt][nt][1] + bb.y;
            float v1x = acc[mt][nt][2] + bb.x, v1y = acc[mt][nt][3] + bb.y;
            if constexpr (HALF_OUT) {
                if (d0 >= 0) {
                    __half2 hp; hp.x = __float2half_rn(v0x); hp.y = __float2half_rn(v0y);
                    *(__half2*)&Chi[(size_t)d0 * DM + c] = hp;
                }
                if (d1 >= 0) {
                    __half2 hq; hq.x = __float2half_rn(v1x); hq.y = __float2half_rn(v1y);
                    *(__half2*)&Chi[(size_t)d1 * DM + c] = hq;
                }
            } else {
                float2 o0 = { v0x, v0y }, o1 = { v1x, v1y };
                *(float2*)&Cf[(size_t)r * DM + c] = o0;
                *(float2*)&Cf[(size_t)(r + 8) * DM + c] = o1;
            }
        }
    }
}

__global__ __launch_bounds__(256, 2)
void qkv_tc_kernel(const float* __restrict__ bq, const float* __restrict__ bk,
                   const float* __restrict__ bv) {
    int z = blockIdx.z;
    const __half* Bh = g_wth + (size_t)z * DM * DM;
    const float* bias = (z == 0) ? bq : (z == 1) ? bk : bv;
    __half* Chi = (z == 0) ? g_qhi : (z == 1) ? g_ckhi : g_cvhi;
    const int* remap = (z == 0) ? nullptr : g_rank;
    gemm_tc_body<true>(g_xhi, Bh, bias, nullptr, Chi, remap);
}

__global__ __launch_bounds__(256, 2)
void oproj_tc_kernel(const float* __restrict__ bo, float* __restrict__ out) {
    gemm_tc_body<false>(g_ahi, g_wth + (size_t)3 * DM * DM, bo, out,
                        nullptr, nullptr);
}

// ---------------- flash attention: 2-stage cp.async (proven R13) --------------
#define KST 72
#define ASEG (64 * KST)
#define ASTG (2 * ASEG)              // Kh, Vh
#define ATT_SMEM (2 * ASTG * 2 + 2 * 64 * 4)   // 37376 bytes

__global__ __launch_bounds__(256, 2)
void attn_tc_kernel() {
    extern __shared__ __half asmem[];
    float* Msb = (float*)(asmem + 2 * ASTG);   // [2][64]

    const int tid = threadIdx.x;
    const int lane = tid & 31, warp = tid >> 5;
    const int grp = lane >> 2, tig = lane & 3;
    const int qb = blockIdx.x, bh = blockIdx.y;
    const int b = bh >> 4, h = bh & 15;
    const int row0 = b * S_LEN + qb * 128;
    const int wm = warp * 16;

    const int cnt = g_kcnt[b];
    const int nblk = (cnt + 63) >> 6;

    const uint32_t sb = smem_u32(asmem);
    const uint32_t msb = smem_u32(Msb);
    const int pr = tid >> 3, pc = (tid & 7) * 8;

    uint32_t qh[4][4];
    {
        const size_t r0 = (size_t)(row0 + wm + grp) * DM;
        const size_t r1 = r0 + 8 * DM;
#pragma unroll
        for (int kc = 0; kc < 4; ++kc) {
            int d = h * DH + kc * 16 + tig * 2;
            qh[kc][0] = *(const uint32_t*)&g_qhi[r0 + d];
            qh[kc][1] = *(const uint32_t*)&g_qhi[r1 + d];
            qh[kc][2] = *(const uint32_t*)&g_qhi[r0 + d + 8];
            qh[kc][3] = *(const uint32_t*)&g_qhi[r1 + d + 8];
        }
    }

    float o[8][4];
#pragma unroll
    for (int nt = 0; nt < 8; ++nt)
#pragma unroll
        for (int e = 0; e < 4; ++e) o[nt][e] = 0.0f;
    float m0 = -1e30f, m1 = -1e30f, l0 = 0.0f, l1 = 0.0f;

    auto load_stage = [&](int kb, int s) {
        const size_t gbase = (size_t)(b * S_LEN + kb * 64) * DM + h * DH;
        const uint32_t sbase = sb + (uint32_t)s * (ASTG * 2);
        const size_t g0 = gbase + (size_t)pr * DM + pc;
        const size_t g1 = gbase + (size_t)(pr + 32) * DM + pc;
        const uint32_t s0 = (uint32_t)(pr * KST + pc) * 2;
        const uint32_t s1 = (uint32_t)((pr + 32) * KST + pc) * 2;
        cpa16(sbase + s0,            &g_ckhi[g0]);
        cpa16(sbase + s1,            &g_ckhi[g1]);
        cpa16(sbase + ASEG * 2 + s0, &g_cvhi[g0]);
        cpa16(sbase + ASEG * 2 + s1, &g_cvhi[g1]);
        if (tid < 16)
            cpa16(msb + (uint32_t)s * 256 + tid * 16,
                  &g_cmask[b * S_LEN + kb * 64 + tid * 4]);
    };

    load_stage(0, 0);
    CP_COMMIT();

    for (int kb = 0; kb < nblk; ++kb) {
        const int cur = kb & 1;
        if (kb + 1 < nblk) {
            load_stage(kb + 1, cur ^ 1);
            CP_COMMIT();
            CP_WAIT(1);
        } else {
            CP_WAIT(0);
        }
        __syncthreads();

        const __half* Kh = asmem + (size_t)cur * ASTG;
        const __half* Vh = Kh + ASEG;
        const float* Ms = Msb + cur * 64;

        float s[8][4];
#pragma unroll
        for (int nt = 0; nt < 8; ++nt)
#pragma unroll
            for (int e = 0; e < 4; ++e) s[nt][e] = 0.0f;

#pragma unroll
        for (int kc = 0; kc < 4; ++kc) {
            const int kof = kc * 16 + tig * 2;
#pragma unroll
            for (int nt = 0; nt < 8; ++nt) {
                const int nr = nt * 8 + grp;
                uint32_t b0 = *(const uint32_t*)&Kh[nr * KST + kof];
                uint32_t b1 = *(const uint32_t*)&Kh[nr * KST + kof + 8];
                MMA_F16(s[nt], qh[kc], b0, b1);
            }
        }

        float tmax0 = -1e30f, tmax1 = -1e30f;
#pragma unroll
        for (int nt = 0; nt < 8; ++nt) {
            float2 mv = *(const float2*)&Ms[nt * 8 + tig * 2];
            s[nt][0] = fmaf(s[nt][0], 0.125f, mv.x);
            s[nt][1] = fmaf(s[nt][1], 0.125f, mv.y);
            s[nt][2] = fmaf(s[nt][2], 0.125f, mv.x);
            s[nt][3] = fmaf(s[nt][3], 0.125f, mv.y);
            tmax0 = fmaxf(tmax0, fmaxf(s[nt][0], s[nt][1]));
            tmax1 = fmaxf(tmax1, fmaxf(s[nt][2], s[nt][3]));
        }
        tmax0 = fmaxf(tmax0, __shfl_xor_sync(0xffffffffu, tmax0, 1));
        tmax0 = fmaxf(tmax0, __shfl_xor_sync(0xffffffffu, tmax0, 2));
        tmax1 = fmaxf(tmax1, __shfl_xor_sync(0xffffffffu, tmax1, 1));
        tmax1 = fmaxf(tmax1, __shfl_xor_sync(0xffffffffu, tmax1, 2));

        float mn0 = fmaxf(m0, tmax0), mn1 = fmaxf(m1, tmax1);
        float al0 = __expf(m0 - mn0), al1 = __expf(m1 - mn1);
        m0 = mn0; m1 = mn1;

        float rs0 = 0.0f, rs1 = 0.0f;
        uint32_t pa[8], pb[8];
#pragma unroll
        for (int nt = 0; nt < 8; ++nt) {
            float p0 = __expf(s[nt][0] - mn0);
            float p1 = __expf(s[nt][1] - mn0);
            float p2 = __expf(s[nt][2] - mn1);
            float p3 = __expf(s[nt][3] - mn1);
            rs0 += p0 + p1; rs1 += p2 + p3;
            pa[nt] = pack_h2(p0, p1);
            pb[nt] = pack_h2(p2, p3);
        }
        rs0 += __shfl_xor_sync(0xffffffffu, rs0, 1);
        rs0 += __shfl_xor_sync(0xffffffffu, rs0, 2);
        rs1 += __shfl_xor_sync(0xffffffffu, rs1, 1);
        rs1 += __shfl_xor_sync(0xffffffffu, rs1, 2);
        l0 = l0 * al0 + rs0;
        l1 = l1 * al1 + rs1;

#pragma unroll
        for (int nt = 0; nt < 8; ++nt) {
            o[nt][0] *= al0; o[nt][1] *= al0;
            o[nt][2] *= al1; o[nt][3] *= al1;
        }

        const int lrow = (lane & 7) + 8 * ((lane >> 3) & 1);
        const int lcol = 8 * (lane >> 4);
#pragma unroll
        for (int kc2 = 0; kc2 < 4; ++kc2) {
            uint32_t a[4] = { pa[kc2 * 2], pb[kc2 * 2], pa[kc2 * 2 + 1], pb[kc2 * 2 + 1] };
#pragma unroll
            for (int dp = 0; dp < 4; ++dp) {
                uint32_t v0, v1, v2, v3;
                uint32_t ad = smem_u32(&Vh[(kc2 * 16 + lrow) * KST + dp * 16 + lcol]);
                LDMATRIX_X4_TRANS(v0, v1, v2, v3, ad);
                MMA_F16(o[dp * 2],     a, v0, v1);
                MMA_F16(o[dp * 2 + 1], a, v2, v3);
            }
        }
        __syncthreads();
    }

    // ---- epilogue: normalize, write fp16 for oproj ----
    float inv0 = 1.0f / l0, inv1 = 1.0f / l1;
    const size_t r0 = (size_t)(row0 + wm + grp) * DM;
    const size_t r1 = r0 + 8 * DM;
#pragma unroll
    for (int nt = 0; nt < 8; ++nt) {
        int c = h * DH + nt * 8 + tig * 2;
        __half2 hp; hp.x = __float2half_rn(o[nt][0] * inv0);
                    hp.y = __float2half_rn(o[nt][1] * inv0);
        *(__half2*)&g_ahi[r0 + c] = hp;
        __half2 hq; hq.x = __float2half_rn(o[nt][2] * inv1);
                    hq.y = __float2half_rn(o[nt][3] * inv1);
        *(__half2*)&g_ahi[r1 + c] = hq;
    }
}

// ---------------- launch -----------------------------------------------------
extern "C" void kernel_launch(void* const* d_in, const int* in_sizes, int n_in,
                              void* d_out, int out_size) {
    const float* x  = (const float*)d_in[0];
    const void*  mk = d_in[1];
    const float* Wq = (const float*)d_in[2];
    const float* bq = (const float*)d_in[3];
    const float* Wk = (const float*)d_in[4];
    const float* bk = (const float*)d_in[5];
    const float* Wv = (const float*)d_in[6];
    const float* bv = (const float*)d_in[7];
    const float* Wo = (const float*)d_in[8];
    const float* bo = (const float*)d_in[9];
    float* out = (float*)d_out;

    scan_mask_kernel<<<B_SZ, 256>>>(mk);

    prep_w_kernel<<<dim3(32, 32, 4), dim3(32, 8)>>>(Wq, Wk, Wv, Wo);
    conv_x_kernel<<<MROWS * DM / 8 / 256, 256>>>((const float4*)x);

    cudaFuncSetAttribute(qkv_tc_kernel,
                         cudaFuncAttributeMaxDynamicSharedMemorySize, GEMM_SMEM);
    cudaFuncSetAttribute(oproj_tc_kernel,
                         cudaFuncAttributeMaxDynamicSharedMemorySize, GEMM_SMEM);
    cudaFuncSetAttribute(attn_tc_kernel,
                         cudaFuncAttributeMaxDynamicSharedMemorySize, ATT_SMEM);

    qkv_tc_kernel<<<dim3(DM / 128, MROWS / 128, 3), 256, GEMM_SMEM>>>(bq, bk, bv);

    attn_tc_kernel<<<dim3(S_LEN / 128, B_SZ * NH), 256, ATT_SMEM>>>();

    oproj_tc_kernel<<<dim3(DM / 128, MROWS / 128), 256, GEMM_SMEM>>>(bo, out);
}

// round 16
// speedup vs baseline: 1.6412x; 1.0826x over previous
#include <cuda_runtime.h>
#include <cuda_bf16.h>
#include <cuda_fp16.h>
#include <cstdint>

#define S_LEN 2048
#define B_SZ 4
#define NH 16
#define DH 64
#define DM 1024
#define MROWS (B_SZ * S_LEN)   // 8192
#define GK 1024

// ---------------- scratch (device globals; device-code references ONLY) -----
// Compacted-K/V padding rows (rank >= kcnt) are never written; they stay at
// the guaranteed zero-init of __device__ globals, and cmask=-1e30 zeroes them.
__device__ int   g_kcnt[B_SZ];
__device__ int   g_rank[B_SZ * S_LEN];    // global dest row or -1
__device__ float g_cmask[B_SZ * S_LEN];

__device__ __half g_xhi[MROWS * DM];
__device__ __half g_ahi[MROWS * DM];
__device__ __half g_wth[4 * DM * DM];     // W^T fp16, [N][K] K-major

__device__ __half g_qhi[MROWS * DM];
__device__ __half g_ckhi[MROWS * DM];     // compacted K (written by GEMM)
__device__ __half g_cvhi[MROWS * DM];     // compacted V (written by GEMM)

// ---------------- PTX helpers ------------------------------------------------
__device__ __forceinline__ uint32_t smem_u32(const void* p) {
    uint32_t a;
    asm("{ .reg .u64 t; cvta.to.shared.u64 t, %1; cvt.u32.u64 %0, t; }"
        : "=r"(a) : "l"(p));
    return a;
}

#define MMA_F16(c, a, b0, b1)                                               \
    asm volatile("mma.sync.aligned.m16n8k16.row.col.f32.f16.f16.f32 "       \
                 "{%0,%1,%2,%3}, {%4,%5,%6,%7}, {%8,%9}, {%0,%1,%2,%3};"    \
                 : "+f"((c)[0]), "+f"((c)[1]), "+f"((c)[2]), "+f"((c)[3])   \
                 : "r"((a)[0]), "r"((a)[1]), "r"((a)[2]), "r"((a)[3]),      \
                   "r"(b0), "r"(b1))

#define LDMATRIX_X4(r0, r1, r2, r3, addr)                                   \
    asm volatile("ldmatrix.sync.aligned.m8n8.x4.shared.b16 "                \
                 "{%0,%1,%2,%3}, [%4];"                                     \
                 : "=r"(r0), "=r"(r1), "=r"(r2), "=r"(r3) : "r"(addr))

#define LDMATRIX_X4_TRANS(r0, r1, r2, r3, addr)                             \
    asm volatile("ldmatrix.sync.aligned.m8n8.x4.trans.shared.b16 "          \
                 "{%0,%1,%2,%3}, [%4];"                                     \
                 : "=r"(r0), "=r"(r1), "=r"(r2), "=r"(r3) : "r"(addr))

__device__ __forceinline__ void cpa16(uint32_t dst, const void* src) {
    asm volatile("cp.async.ca.shared.global [%0], [%1], 16;"
                 :: "r"(dst), "l"(src));
}
#define CP_COMMIT()  asm volatile("cp.async.commit_group;" ::: "memory")
#define CP_WAIT(n)   asm volatile("cp.async.wait_group %0;" :: "n"(n) : "memory")

__device__ __forceinline__ uint32_t pack_h2(float a, float b) {
    __half2 h = __floats2half2_rn(a, b);
    return *(uint32_t*)&h;
}

// ---------------- mask scan (dtype detect fused in) ---------------------------
__global__ __launch_bounds__(256)
void scan_mask_kernel(const void* __restrict__ mraw) {
    __shared__ int ssum[256];
    __shared__ int s_nonbin, s_off;
    const int b = blockIdx.x;
    const int tid = threadIdx.x;

    if (tid == 0) { s_nonbin = 0; s_off = 0; }
    __syncthreads();
    {
        const unsigned char* mb = (const unsigned char*)mraw;
        int nb = 0, off = 0;
        for (int i = tid; i < B_SZ * S_LEN; i += 256) {
            unsigned char v = mb[i];
            if (v > 1) nb = 1;
            if ((i & 3) && v) off = 1;
        }
        if (nb) atomicOr(&s_nonbin, 1);
        if (off) atomicOr(&s_off, 1);
    }
    __syncthreads();
    const int mode = s_nonbin ? 2 : (s_off ? 1 : 0);

    int flags[8], loc = 0;
#pragma unroll
    for (int j = 0; j < 8; ++j) {
        int i = b * S_LEN + tid * 8 + j;
        bool t;
        if (mode == 0)      t = ((const int*)mraw)[i] != 0;
        else if (mode == 1) t = ((const unsigned char*)mraw)[i] != 0;
        else                t = ((const float*)mraw)[i] != 0.0f;
        flags[j] = t ? 1 : 0;
        loc += flags[j];
    }
    ssum[tid] = loc;
    __syncthreads();
    for (int off = 1; off < 256; off <<= 1) {
        int v = (tid >= off) ? ssum[tid - off] : 0;
        __syncthreads();
        ssum[tid] += v;
        __syncthreads();
    }
    int base = (tid > 0) ? ssum[tid - 1] : 0;
    const int cnt = ssum[255];
#pragma unroll
    for (int j = 0; j < 8; ++j) {
        int i = tid * 8 + j;
        g_rank[b * S_LEN + i] = flags[j] ? (b * S_LEN + base++) : -1;
        g_cmask[b * S_LEN + i] = (i < cnt) ? 0.0f : -1e30f;
    }
    if (tid == 255) g_kcnt[b] = cnt;
}

// ---------------- fp32 -> fp16 (x), 8 elems/thread ----------------------------
__global__ __launch_bounds__(256)
void conv_x_kernel(const float4* __restrict__ src) {
    int i = blockIdx.x * blockDim.x + threadIdx.x;
    float4 a = src[2 * i], c = src[2 * i + 1];
    __half2 h0 = __floats2half2_rn(a.x, a.y);
    __half2 h1 = __floats2half2_rn(a.z, a.w);
    __half2 h2 = __floats2half2_rn(c.x, c.y);
    __half2 h3 = __floats2half2_rn(c.z, c.w);
    uint4 o = { *(uint32_t*)&h0, *(uint32_t*)&h1, *(uint32_t*)&h2, *(uint32_t*)&h3 };
    *(uint4*)&g_xhi[(size_t)i * 8] = o;
}

// ---------------- W transpose + fp16 -----------------------------------------
__global__ __launch_bounds__(256)
void prep_w_kernel(const float* __restrict__ Wq, const float* __restrict__ Wk,
                   const float* __restrict__ Wv, const float* __restrict__ Wo) {
    __shared__ float t[32][33];
    int z = blockIdx.z;
    const float* W = (z == 0) ? Wq : (z == 1) ? Wk : (z == 2) ? Wv : Wo;
    __half* oh = g_wth + (size_t)z * DM * DM;
    int x0 = blockIdx.x * 32, y0 = blockIdx.y * 32;
    int tx = threadIdx.x, ty = threadIdx.y;   // (32, 8)
#pragma unroll
    for (int j = 0; j < 4; ++j)
        t[ty + j * 8][tx] = W[(size_t)(y0 + ty + j * 8) * DM + x0 + tx];
    __syncthreads();
#pragma unroll
    for (int j = 0; j < 4; ++j) {
        float v = t[tx][ty + j * 8];
        oh[(size_t)(x0 + ty + j * 8) * DM + y0 + tx] = __float2half_rn(v);
    }
}

// ---------------- mma.sync fp16 GEMM, 2-stage cp.async + ldmatrix frags ------
#define AS_STRIDE 40
#define SEG (128 * AS_STRIDE)
#define SEGB (SEG * 2)
#define STAGEB (2 * SEGB)            // A, B
#define GEMM_SMEM (2 * STAGEB)       // 40960 bytes
#define ROWB (AS_STRIDE * 2)         // 80 bytes per smem row

template <bool HALF_OUT>
__device__ __forceinline__ void gemm_tc_body(const __half* __restrict__ Ah_g,
                                             const __half* __restrict__ Bh_g,
                                             const float* __restrict__ bias,
                                             float* __restrict__ Cf,
                                             __half* __restrict__ Chi,
                                             const int* __restrict__ remap) {
    extern __shared__ __half smh[];

    const int tid  = threadIdx.x;
    const int lane = tid & 31, warp = tid >> 5;
    const int wm = (warp & 3) * 32;
    const int wn = (warp >> 2) * 64;
    const int m0 = blockIdx.y * 128;
    const int n0 = blockIdx.x * 128;
    const int grp = lane >> 2;
    const int tig = lane & 3;

    const uint32_t sb = smem_u32(smh);
    const int r0l = tid >> 2, q0l = tid & 3;
    const int r1l = (tid + 256) >> 2;
    const uint32_t soff0 = (uint32_t)(r0l * AS_STRIDE + q0l * 8) * 2;
    const uint32_t soff1 = (uint32_t)(r1l * AS_STRIDE + q0l * 8) * 2;

    // ldmatrix source offsets (relative to stage base / B region)
    const uint32_t a_frag = (uint32_t)((wm + (lane & 7) + ((lane >> 3) & 1) * 8) * AS_STRIDE
                                       + (lane >> 4) * 8) * 2;
    const uint32_t b_frag = (uint32_t)((wn + (lane & 7) + ((lane >> 4) & 1) * 8) * AS_STRIDE
                                       + ((lane >> 3) & 1) * 8) * 2;

    float acc[2][8][4];
#pragma unroll
    for (int mt = 0; mt < 2; ++mt)
#pragma unroll
        for (int nt = 0; nt < 8; ++nt)
#pragma unroll
            for (int e = 0; e < 4; ++e) acc[mt][nt][e] = 0.0f;

    auto load_stage = [&](int kt, int s) {
        const uint32_t base = sb + (uint32_t)s * STAGEB;
        const size_t ga0 = (size_t)(m0 + r0l) * GK + kt * 32 + q0l * 8;
        const size_t ga1 = (size_t)(m0 + r1l) * GK + kt * 32 + q0l * 8;
        const size_t gb0 = (size_t)(n0 + r0l) * GK + kt * 32 + q0l * 8;
        const size_t gb1 = (size_t)(n0 + r1l) * GK + kt * 32 + q0l * 8;
        cpa16(base + soff0,        &Ah_g[ga0]);
        cpa16(base + SEGB + soff0, &Bh_g[gb0]);
        cpa16(base + soff1,        &Ah_g[ga1]);
        cpa16(base + SEGB + soff1, &Bh_g[gb1]);
    };

    load_stage(0, 0);
    CP_COMMIT();

    for (int kt = 0; kt < GK / 32; ++kt) {
        const int cur = kt & 1;
        if (kt + 1 < GK / 32) {
            load_stage(kt + 1, cur ^ 1);
            CP_COMMIT();
            CP_WAIT(1);
        } else {
            CP_WAIT(0);
        }
        __syncthreads();

        const uint32_t abase = sb + (uint32_t)cur * STAGEB + a_frag;
        const uint32_t bbase = sb + (uint32_t)cur * STAGEB + SEGB + b_frag;

#pragma unroll
        for (int ks = 0; ks < 2; ++ks) {
            const uint32_t ko = (uint32_t)ks * 32;   // 16 halfs
            uint32_t bh[8][2];
#pragma unroll
            for (int p = 0; p < 4; ++p)
                LDMATRIX_X4(bh[2 * p][0], bh[2 * p][1], bh[2 * p + 1][0], bh[2 * p + 1][1],
                            bbase + (uint32_t)p * 16 * ROWB + ko);
#pragma unroll
            for (int mt = 0; mt < 2; ++mt) {
                uint32_t a_h[4];
                LDMATRIX_X4(a_h[0], a_h[1], a_h[2], a_h[3],
                            abase + (uint32_t)mt * 16 * ROWB + ko);
#pragma unroll
                for (int nt = 0; nt < 8; ++nt)
                    MMA_F16(acc[mt][nt], a_h, bh[nt][0], bh[nt][1]);
            }
        }
        __syncthreads();
    }

#pragma unroll
    for (int mt = 0; mt < 2; ++mt) {
        const int r = m0 + wm + mt * 16 + grp;
        int d0 = r, d1 = r + 8;
        if (HALF_OUT && remap) {
            d0 = remap[r];
            d1 = remap[r + 8];
        }
#pragma unroll
        for (int nt = 0; nt < 8; ++nt) {
            int c = n0 + wn + nt * 8 + tig * 2;
            float2 bb = *(const float2*)&bias[c];
            float v0x = acc[mt][nt][0] + bb.x, v0y = acc[mt][nt][1] + bb.y;
            float v1x = acc[mt][nt][2] + bb.x, v1y = acc[mt][nt][3] + bb.y;
            if constexpr (HALF_OUT) {
                if (d0 >= 0) {
                    __half2 hp; hp.x = __float2half_rn(v0x); hp.y = __float2half_rn(v0y);
                    *(__half2*)&Chi[(size_t)d0 * DM + c] = hp;
                }
                if (d1 >= 0) {
                    __half2 hq; hq.x = __float2half_rn(v1x); hq.y = __float2half_rn(v1y);
                    *(__half2*)&Chi[(size_t)d1 * DM + c] = hq;
                }
            } else {
                float2 o0 = { v0x, v0y }, o1 = { v1x, v1y };
                *(float2*)&Cf[(size_t)r * DM + c] = o0;
                *(float2*)&Cf[(size_t)(r + 8) * DM + c] = o1;
            }
        }
    }
}

__global__ __launch_bounds__(256, 2)
void qkv_tc_kernel(const float* __restrict__ bq, const float* __restrict__ bk,
                   const float* __restrict__ bv) {
    int z = blockIdx.z;
    const __half* Bh = g_wth + (size_t)z * DM * DM;
    const float* bias = (z == 0) ? bq : (z == 1) ? bk : bv;
    __half* Chi = (z == 0) ? g_qhi : (z == 1) ? g_ckhi : g_cvhi;
    const int* remap = (z == 0) ? nullptr : g_rank;
    gemm_tc_body<true>(g_xhi, Bh, bias, nullptr, Chi, remap);
}

__global__ __launch_bounds__(256, 2)
void oproj_tc_kernel(const float* __restrict__ bo, float* __restrict__ out) {
    gemm_tc_body<false>(g_ahi, g_wth + (size_t)3 * DM * DM, bo, out,
                        nullptr, nullptr);
}

// ---------------- flash attention: 2-stage cp.async + ldmatrix K frags -------
#define KST 72
#define KROWB (KST * 2)              // 144 bytes per smem row
#define ASEG (64 * KST)
#define ASTG (2 * ASEG)              // Kh, Vh
#define ATT_SMEM (2 * ASTG * 2 + 2 * 64 * 4)   // 37376 bytes

__global__ __launch_bounds__(256, 2)
void attn_tc_kernel() {
    extern __shared__ __half asmem[];
    float* Msb = (float*)(asmem + 2 * ASTG);   // [2][64]

    const int tid = threadIdx.x;
    const int lane = tid & 31, warp = tid >> 5;
    const int grp = lane >> 2, tig = lane & 3;
    const int qb = blockIdx.x, bh = blockIdx.y;
    const int b = bh >> 4, h = bh & 15;
    const int row0 = b * S_LEN + qb * 128;
    const int wm = warp * 16;

    const int cnt = g_kcnt[b];
    const int nblk = (cnt + 63) >> 6;

    const uint32_t sb = smem_u32(asmem);
    const uint32_t msb = smem_u32(Msb);
    const int pr = tid >> 3, pc = (tid & 7) * 8;

    // ldmatrix K-fragment offset (relative to K region base)
    const uint32_t k_frag = (uint32_t)(((lane & 7) + ((lane >> 4) & 1) * 8) * KST
                                       + ((lane >> 3) & 1) * 8) * 2;

    uint32_t qh[4][4];
    {
        const size_t r0 = (size_t)(row0 + wm + grp) * DM;
        const size_t r1 = r0 + 8 * DM;
#pragma unroll
        for (int kc = 0; kc < 4; ++kc) {
            int d = h * DH + kc * 16 + tig * 2;
            qh[kc][0] = *(const uint32_t*)&g_qhi[r0 + d];
            qh[kc][1] = *(const uint32_t*)&g_qhi[r1 + d];
            qh[kc][2] = *(const uint32_t*)&g_qhi[r0 + d + 8];
            qh[kc][3] = *(const uint32_t*)&g_qhi[r1 + d + 8];
        }
    }

    float o[8][4];
#pragma unroll
    for (int nt = 0; nt < 8; ++nt)
#pragma unroll
        for (int e = 0; e < 4; ++e) o[nt][e] = 0.0f;
    float m0 = -1e30f, m1 = -1e30f, l0 = 0.0f, l1 = 0.0f;

    auto load_stage = [&](int kb, int s) {
        const size_t gbase = (size_t)(b * S_LEN + kb * 64) * DM + h * DH;
        const uint32_t sbase = sb + (uint32_t)s * (ASTG * 2);
        const size_t g0 = gbase + (size_t)pr * DM + pc;
        const size_t g1 = gbase + (size_t)(pr + 32) * DM + pc;
        const uint32_t s0 = (uint32_t)(pr * KST + pc) * 2;
        const uint32_t s1 = (uint32_t)((pr + 32) * KST + pc) * 2;
        cpa16(sbase + s0,            &g_ckhi[g0]);
        cpa16(sbase + s1,            &g_ckhi[g1]);
        cpa16(sbase + ASEG * 2 + s0, &g_cvhi[g0]);
        cpa16(sbase + ASEG * 2 + s1, &g_cvhi[g1]);
        if (tid < 16)
            cpa16(msb + (uint32_t)s * 256 + tid * 16,
                  &g_cmask[b * S_LEN + kb * 64 + tid * 4]);
    };

    load_stage(0, 0);
    CP_COMMIT();

    for (int kb = 0; kb < nblk; ++kb) {
        const int cur = kb & 1;
        if (kb + 1 < nblk) {
            load_stage(kb + 1, cur ^ 1);
            CP_COMMIT();
            CP_WAIT(1);
        } else {
            CP_WAIT(0);
        }
        __syncthreads();

        const __half* Kh = asmem + (size_t)cur * ASTG;
        const __half* Vh = Kh + ASEG;
        const float* Ms = Msb + cur * 64;
        const uint32_t kbase = sb + (uint32_t)cur * (ASTG * 2) + k_frag;

        float s[8][4];
#pragma unroll
        for (int nt = 0; nt < 8; ++nt)
#pragma unroll
            for (int e = 0; e < 4; ++e) s[nt][e] = 0.0f;

#pragma unroll
        for (int kc = 0; kc < 4; ++kc) {
            const uint32_t ko = (uint32_t)kc * 32;   // 16 halfs
            uint32_t bhf[8][2];
#pragma unroll
            for (int p = 0; p < 4; ++p)
                LDMATRIX_X4(bhf[2 * p][0], bhf[2 * p][1], bhf[2 * p + 1][0], bhf[2 * p + 1][1],
                            kbase + (uint32_t)p * 16 * KROWB + ko);
#pragma unroll
            for (int nt = 0; nt < 8; ++nt)
                MMA_F16(s[nt], qh[kc], bhf[nt][0], bhf[nt][1]);
        }

        float tmax0 = -1e30f, tmax1 = -1e30f;
#pragma unroll
        for (int nt = 0; nt < 8; ++nt) {
            float2 mv = *(const float2*)&Ms[nt * 8 + tig * 2];
            s[nt][0] = fmaf(s[nt][0], 0.125f, mv.x);
            s[nt][1] = fmaf(s[nt][1], 0.125f, mv.y);
            s[nt][2] = fmaf(s[nt][2], 0.125f, mv.x);
            s[nt][3] = fmaf(s[nt][3], 0.125f, mv.y);
            tmax0 = fmaxf(tmax0, fmaxf(s[nt][0], s[nt][1]));
            tmax1 = fmaxf(tmax1, fmaxf(s[nt][2], s[nt][3]));
        }
        tmax0 = fmaxf(tmax0, __shfl_xor_sync(0xffffffffu, tmax0, 1));
        tmax0 = fmaxf(tmax0, __shfl_xor_sync(0xffffffffu, tmax0, 2));
        tmax1 = fmaxf(tmax1, __shfl_xor_sync(0xffffffffu, tmax1, 1));
        tmax1 = fmaxf(tmax1, __shfl_xor_sync(0xffffffffu, tmax1, 2));

        float mn0 = fmaxf(m0, tmax0), mn1 = fmaxf(m1, tmax1);
        float al0 = __expf(m0 - mn0), al1 = __expf(m1 - mn1);
        m0 = mn0; m1 = mn1;

        float rs0 = 0.0f, rs1 = 0.0f;
        uint32_t pa[8], pb[8];
#pragma unroll
        for (int nt = 0; nt < 8; ++nt) {
            float p0 = __expf(s[nt][0] - mn0);
            float p1 = __expf(s[nt][1] - mn0);
            float p2 = __expf(s[nt][2] - mn1);
            float p3 = __expf(s[nt][3] - mn1);
            rs0 += p0 + p1; rs1 += p2 + p3;
            pa[nt] = pack_h2(p0, p1);
            pb[nt] = pack_h2(p2, p3);
        }
        rs0 += __shfl_xor_sync(0xffffffffu, rs0, 1);
        rs0 += __shfl_xor_sync(0xffffffffu, rs0, 2);
        rs1 += __shfl_xor_sync(0xffffffffu, rs1, 1);
        rs1 += __shfl_xor_sync(0xffffffffu, rs1, 2);
        l0 = l0 * al0 + rs0;
        l1 = l1 * al1 + rs1;

#pragma unroll
        for (int nt = 0; nt < 8; ++nt) {
            o[nt][0] *= al0; o[nt][1] *= al0;
            o[nt][2] *= al1; o[nt][3] *= al1;
        }

        const int lrow = (lane & 7) + 8 * ((lane >> 3) & 1);
        const int lcol = 8 * (lane >> 4);
#pragma unroll
        for (int kc2 = 0; kc2 < 4; ++kc2) {
            uint32_t a[4] = { pa[kc2 * 2], pb[kc2 * 2], pa[kc2 * 2 + 1], pb[kc2 * 2 + 1] };
#pragma unroll
            for (int dp = 0; dp < 4; ++dp) {
                uint32_t v0, v1, v2, v3;
                uint32_t ad = smem_u32(&Vh[(kc2 * 16 + lrow) * KST + dp * 16 + lcol]);
                LDMATRIX_X4_TRANS(v0, v1, v2, v3, ad);
                MMA_F16(o[dp * 2],     a, v0, v1);
                MMA_F16(o[dp * 2 + 1], a, v2, v3);
            }
        }
        __syncthreads();
    }

    // ---- epilogue: normalize, write fp16 for oproj ----
    float inv0 = 1.0f / l0, inv1 = 1.0f / l1;
    const size_t r0 = (size_t)(row0 + wm + grp) * DM;
    const size_t r1 = r0 + 8 * DM;
#pragma unroll
    for (int nt = 0; nt < 8; ++nt) {
        int c = h * DH + nt * 8 + tig * 2;
        __half2 hp; hp.x = __float2half_rn(o[nt][0] * inv0);
                    hp.y = __float2half_rn(o[nt][1] * inv0);
        *(__half2*)&g_ahi[r0 + c] = hp;
        __half2 hq; hq.x = __float2half_rn(o[nt][2] * inv1);
                    hq.y = __float2half_rn(o[nt][3] * inv1);
        *(__half2*)&g_ahi[r1 + c] = hq;
    }
}

// ---------------- launch -----------------------------------------------------
extern "C" void kernel_launch(void* const* d_in, const int* in_sizes, int n_in,
                              void* d_out, int out_size) {
    const float* x  = (const float*)d_in[0];
    const void*  mk = d_in[1];
    const float* Wq = (const float*)d_in[2];
    const float* bq = (const float*)d_in[3];
    const float* Wk = (const float*)d_in[4];
    const float* bk = (const float*)d_in[5];
    const float* Wv = (const float*)d_in[6];
    const float* bv = (const float*)d_in[7];
    const float* Wo = (const float*)d_in[8];
    const float* bo = (const float*)d_in[9];
    float* out = (float*)d_out;

    scan_mask_kernel<<<B_SZ, 256>>>(mk);

    prep_w_kernel<<<dim3(32, 32, 4), dim3(32, 8)>>>(Wq, Wk, Wv, Wo);
    conv_x_kernel<<<MROWS * DM / 8 / 256, 256>>>((const float4*)x);

    cudaFuncSetAttribute(qkv_tc_kernel,
                         cudaFuncAttributeMaxDynamicSharedMemorySize, GEMM_SMEM);
    cudaFuncSetAttribute(oproj_tc_kernel,
                         cudaFuncAttributeMaxDynamicSharedMemorySize, GEMM_SMEM);
    cudaFuncSetAttribute(attn_tc_kernel,
                         cudaFuncAttributeMaxDynamicSharedMemorySize, ATT_SMEM);

    qkv_tc_kernel<<<dim3(DM / 128, MROWS / 128, 3), 256, GEMM_SMEM>>>(bq, bk, bv);

    attn_tc_kernel<<<dim3(S_LEN / 128, B_SZ * NH), 256, ATT_SMEM>>>();

    oproj_tc_kernel<<<dim3(DM / 128, MROWS / 128), 256, GEMM_SMEM>>>(bo, out);
}